// round 13
// baseline (speedup 1.0000x reference)
#include <cuda_runtime.h>

#define TSEQ 100
#define HHID 200
#define BT   16
#define NTH  224
#define NU   200

typedef unsigned long long u64;

__device__ __forceinline__ u64 pack2(float a, float b) {
    u64 r; asm("mov.b64 %0, {%1, %2};" : "=l"(r) : "f"(a), "f"(b)); return r;
}
__device__ __forceinline__ float2 unpack2(u64 v) {
    float2 f; asm("mov.b64 {%0, %1}, %2;" : "=f"(f.x), "=f"(f.y) : "l"(v)); return f;
}
__device__ __forceinline__ u64 ffma2(u64 a, u64 b, u64 c) {
    u64 d; asm("fma.rn.f32x2 %0, %1, %2, %3;" : "=l"(d) : "l"(a), "l"(b), "l"(c)); return d;
}
__device__ __forceinline__ float ex2f(float x) {
    float y; asm("ex2.approx.ftz.f32 %0, %1;" : "=f"(y) : "f"(x)); return y;
}
__device__ __forceinline__ float rcpf(float x) {
    float y; asm("rcp.approx.ftz.f32 %0, %1;" : "=f"(y) : "f"(x)); return y;
}
__device__ __forceinline__ float sigm(float z) {
    return rcpf(1.0f + ex2f(-1.44269504f * z));
}
__device__ __forceinline__ float tanhf_(float z) {
    return __fmaf_rn(2.0f, rcpf(1.0f + ex2f(-2.88539008f * z)), -1.0f);
}

// z[4 gates][16 rows] += h(SMEM,[k][b]) @ U(GMEM,[k][4H]); this thread owns unit u.
__device__ __forceinline__ void matvec_acc(
    u64 zi[8], u64 zf[8], u64 zg[8], u64 zo[8],
    const float* __restrict__ hs, const float* __restrict__ Uw, int u)
{
    #pragma unroll 2
    for (int k = 0; k < HHID; ++k) {
        const ulonglong2* hp = (const ulonglong2*)(hs + k * BT);
        ulonglong2 p0 = hp[0], p1 = hp[1], p2 = hp[2], p3 = hp[3];
        u64 h8[8] = { p0.x, p0.y, p1.x, p1.y, p2.x, p2.y, p3.x, p3.y };
        const float* wr = Uw + k * 800 + u;
        float a = __ldg(wr), b = __ldg(wr + 200), c = __ldg(wr + 400), d = __ldg(wr + 600);
        u64 wi = pack2(a, a), wf = pack2(b, b), wg = pack2(c, c), wo = pack2(d, d);
        #pragma unroll
        for (int p = 0; p < 8; ++p) {
            zi[p] = ffma2(h8[p], wi, zi[p]);
            zf[p] = ffma2(h8[p], wf, zf[p]);
            zg[p] = ffma2(h8[p], wg, zg[p]);
            zo[p] = ffma2(h8[p], wo, zo[p]);
        }
    }
}

__device__ __forceinline__ void set_bias(
    u64 zi[8], u64 zf[8], u64 zg[8], u64 zo[8],
    const float* __restrict__ bias, int u)
{
    float a = __ldg(bias + u), b = __ldg(bias + 200 + u);
    float c = __ldg(bias + 400 + u), d = __ldg(bias + 600 + u);
    u64 vi = pack2(a, a), vf = pack2(b, b), vg = pack2(c, c), vo = pack2(d, d);
    #pragma unroll
    for (int p = 0; p < 8; ++p) { zi[p] = vi; zf[p] = vf; zg[p] = vg; zo[p] = vo; }
}

__device__ __forceinline__ void gate_update(
    u64 zi[8], u64 zf[8], u64 zg[8], u64 zo[8],
    float c[BT], float* __restrict__ hrow)
{
    float hl[BT];
    #pragma unroll
    for (int p = 0; p < 8; ++p) {
        float2 vi = unpack2(zi[p]), vf = unpack2(zf[p]);
        float2 vg = unpack2(zg[p]), vo = unpack2(zo[p]);
        float cA = sigm(vf.x) * c[2*p]   + sigm(vi.x) * tanhf_(vg.x);
        float cB = sigm(vf.y) * c[2*p+1] + sigm(vi.y) * tanhf_(vg.y);
        c[2*p] = cA; c[2*p+1] = cB;
        hl[2*p]   = sigm(vo.x) * tanhf_(cA);
        hl[2*p+1] = sigm(vo.y) * tanhf_(cB);
    }
    float4* hv = (float4*)hrow;
    #pragma unroll
    for (int q = 0; q < 4; ++q) hv[q] = ((const float4*)hl)[q];
}

__global__ void __launch_bounds__(NTH, 1)
lstm3_kernel(
    const float* __restrict__ x,
    const float* __restrict__ W0, const float* __restrict__ U0, const float* __restrict__ b0,
    const float* __restrict__ W1, const float* __restrict__ U1, const float* __restrict__ b1,
    const float* __restrict__ W2, const float* __restrict__ U2, const float* __restrict__ b2,
    const float* __restrict__ Wfc, const float* __restrict__ bfc,
    float* __restrict__ out, int B)
{
    __shared__ __align__(16) float hs_[3 * HHID * BT];
    __shared__ __align__(16) float xs_[TSEQ * BT];

    const int tid = threadIdx.x;
    const int brow = blockIdx.x * BT;

    for (int i = tid; i < 3 * HHID * BT; i += NTH) hs_[i] = 0.0f;
    for (int i = tid; i < TSEQ * BT; i += NTH) {
        int b = i / TSEQ, t = i - b * TSEQ, gb = brow + b;
        xs_[t * BT + b] = (gb < B) ? x[gb * TSEQ + t] : 0.0f;
    }
    __syncthreads();

    const int u = tid;
    float c0[BT], c1[BT], c2[BT];
    #pragma unroll
    for (int i = 0; i < BT; ++i) { c0[i] = 0.f; c1[i] = 0.f; c2[i] = 0.f; }

    float* h0s = hs_;
    float* h1s = hs_ + HHID * BT;
    float* h2s = hs_ + 2 * HHID * BT;

    for (int t = 0; t < TSEQ; ++t) {
        u64 zi[8], zf[8], zg[8], zo[8];

        // layer 0: z = x_t*W0 + h0@U0 + b0   (input dim 1 -> outer product)
        if (u < NU) {
            set_bias(zi, zf, zg, zo, b0, u);
            float a = __ldg(W0 + u), b = __ldg(W0 + 200 + u);
            float c = __ldg(W0 + 400 + u), d = __ldg(W0 + 600 + u);
            u64 wi = pack2(a, a), wf = pack2(b, b), wg = pack2(c, c), wo = pack2(d, d);
            const ulonglong2* xp = (const ulonglong2*)(xs_ + t * BT);
            ulonglong2 q0 = xp[0], q1 = xp[1], q2 = xp[2], q3 = xp[3];
            u64 xv[8] = { q0.x, q0.y, q1.x, q1.y, q2.x, q2.y, q3.x, q3.y };
            #pragma unroll
            for (int p = 0; p < 8; ++p) {
                zi[p] = ffma2(xv[p], wi, zi[p]);
                zf[p] = ffma2(xv[p], wf, zf[p]);
                zg[p] = ffma2(xv[p], wg, zg[p]);
                zo[p] = ffma2(xv[p], wo, zo[p]);
            }
            matvec_acc(zi, zf, zg, zo, h0s, U0, u);
        }
        __syncthreads();
        if (u < NU) gate_update(zi, zf, zg, zo, c0, h0s + u * BT);
        __syncthreads();

        // layer 1
        if (u < NU) {
            set_bias(zi, zf, zg, zo, b1, u);
            matvec_acc(zi, zf, zg, zo, h0s, W1, u);
            matvec_acc(zi, zf, zg, zo, h1s, U1, u);
        }
        __syncthreads();
        if (u < NU) gate_update(zi, zf, zg, zo, c1, h1s + u * BT);
        __syncthreads();

        // layer 2
        if (u < NU) {
            set_bias(zi, zf, zg, zo, b2, u);
            matvec_acc(zi, zf, zg, zo, h1s, W2, u);
            matvec_acc(zi, zf, zg, zo, h2s, U2, u);
        }
        __syncthreads();
        if (u < NU) gate_update(zi, zf, zg, zo, c2, h2s + u * BT);
        __syncthreads();
    }

    // dense head: y = tanh(h2 @ Wfc + bfc), out[b, j], j in [0,400)
    for (int idx = tid; idx < BT * 400; idx += NTH) {
        int b = idx / 400, j = idx - b * 400;
        int gb = brow + b;
        if (gb >= B) continue;
        float s = __ldg(bfc + j);
        #pragma unroll 4
        for (int k = 0; k < HHID; ++k)
            s = __fmaf_rn(hs_[2 * HHID * BT + k * BT + b], __ldg(Wfc + k * 400 + j), s);
        out[gb * 400 + j] = tanhf_(s);
    }
}

extern "C" void kernel_launch(void* const* d_in, const int* in_sizes, int n_in,
                              void* d_out, int out_size) {
    const float* x   = (const float*)d_in[0];
    const float* W0  = (const float*)d_in[1];
    const float* U0  = (const float*)d_in[2];
    const float* b0  = (const float*)d_in[3];
    const float* W1  = (const float*)d_in[4];
    const float* U1  = (const float*)d_in[5];
    const float* b1  = (const float*)d_in[6];
    const float* W2  = (const float*)d_in[7];
    const float* U2  = (const float*)d_in[8];
    const float* b2  = (const float*)d_in[9];
    const float* Wfc = (const float*)d_in[10];
    const float* bfc = (const float*)d_in[11];
    float* out = (float*)d_out;

    int B = in_sizes[0] / TSEQ;           // x is [B, 100, 1]
    int nblk = (B + BT - 1) / BT;
    lstm3_kernel<<<nblk, NTH>>>(x, W0, U0, b0, W1, U1, b1, W2, U2, b2, Wfc, bfc, out, B);
}

// round 14
// speedup vs baseline: 1.2285x; 1.2285x over previous
#include <cuda_runtime.h>

#define TSEQ 100
#define HHID 200
#define BT   16          // batch rows per CTA
#define NTH  800         // 4 gates x 200 units
#define HPAD 20          // h row stride in floats (padded, 16B-aligned)
#define ZPAD 10          // z row stride in u64 (padded, 16B-aligned)

typedef unsigned long long u64;

// SMEM: hs[3][200][HPAD] floats | zs[800][ZPAD] u64 | xs[100][BT] floats
#define HS_BYTES (3 * HHID * HPAD * 4)
#define ZS_BYTES (NTH * ZPAD * 8)
#define XS_BYTES (TSEQ * BT * 4)
#define SMEM_BYTES (HS_BYTES + ZS_BYTES + XS_BYTES)

__device__ __forceinline__ u64 pack2(float a, float b) {
    u64 r; asm("mov.b64 %0, {%1, %2};" : "=l"(r) : "f"(a), "f"(b)); return r;
}
__device__ __forceinline__ float2 unpack2(u64 v) {
    float2 f; asm("mov.b64 {%0, %1}, %2;" : "=f"(f.x), "=f"(f.y) : "l"(v)); return f;
}
__device__ __forceinline__ u64 ffma2(u64 a, u64 b, u64 c) {
    u64 d; asm("fma.rn.f32x2 %0, %1, %2, %3;" : "=l"(d) : "l"(a), "l"(b), "l"(c)); return d;
}
__device__ __forceinline__ float ex2f(float x) {
    float y; asm("ex2.approx.ftz.f32 %0, %1;" : "=f"(y) : "f"(x)); return y;
}
__device__ __forceinline__ float rcpf(float x) {
    float y; asm("rcp.approx.ftz.f32 %0, %1;" : "=f"(y) : "f"(x)); return y;
}
__device__ __forceinline__ float sigm(float z)  { return rcpf(1.0f + ex2f(-1.44269504f * z)); }
__device__ __forceinline__ float tanhf_(float z){ return __fmaf_rn(2.0f, rcpf(1.0f + ex2f(-2.88539008f * z)), -1.0f); }

// acc[8] (f32x2 over 16 batch rows) += h(SMEM) @ M column (this thread's gate/unit)
__device__ __forceinline__ void mv(u64 acc[8], const float* __restrict__ hL,
                                   const float* __restrict__ M, int tid)
{
    #pragma unroll 2
    for (int k = 0; k < HHID; ++k) {
        float w = __ldg(M + k * 800 + tid);
        u64 wp = pack2(w, w);
        const ulonglong2* hp = (const ulonglong2*)(hL + k * HPAD);
        ulonglong2 a = hp[0], b = hp[1], c = hp[2], d = hp[3];
        acc[0] = ffma2(a.x, wp, acc[0]); acc[1] = ffma2(a.y, wp, acc[1]);
        acc[2] = ffma2(b.x, wp, acc[2]); acc[3] = ffma2(b.y, wp, acc[3]);
        acc[4] = ffma2(c.x, wp, acc[4]); acc[5] = ffma2(c.y, wp, acc[5]);
        acc[6] = ffma2(d.x, wp, acc[6]); acc[7] = ffma2(d.y, wp, acc[7]);
    }
}

__device__ __forceinline__ void set_bias(u64 acc[8], const float* __restrict__ bias, int tid)
{
    float bv = __ldg(bias + tid);
    u64 bp = pack2(bv, bv);
    #pragma unroll
    for (int j = 0; j < 8; ++j) acc[j] = bp;
}

__device__ __forceinline__ void z_store(u64* __restrict__ zs, const u64 acc[8], int tid)
{
    ulonglong2* zr = (ulonglong2*)(zs + tid * ZPAD);
    zr[0] = make_ulonglong2(acc[0], acc[1]);
    zr[1] = make_ulonglong2(acc[2], acc[3]);
    zr[2] = make_ulonglong2(acc[4], acc[5]);
    zr[3] = make_ulonglong2(acc[6], acc[7]);
}

// thread (gu, q) updates cells for unit gu, batch rows 4q..4q+3 of layer hL
__device__ __forceinline__ void gate_phase(const u64* __restrict__ zs, int gu, int q,
                                           float* __restrict__ cl, float* __restrict__ hL)
{
    const ulonglong2* pi = (const ulonglong2*)(zs + (0 * HHID + gu) * ZPAD + 2 * q);
    const ulonglong2* pf = (const ulonglong2*)(zs + (1 * HHID + gu) * ZPAD + 2 * q);
    const ulonglong2* pg = (const ulonglong2*)(zs + (2 * HHID + gu) * ZPAD + 2 * q);
    const ulonglong2* po = (const ulonglong2*)(zs + (3 * HHID + gu) * ZPAD + 2 * q);
    ulonglong2 I = pi[0], F = pf[0], G = pg[0], O = po[0];
    u64 zi2[2] = { I.x, I.y }, zf2[2] = { F.x, F.y };
    u64 zg2[2] = { G.x, G.y }, zo2[2] = { O.x, O.y };
    float hl[4];
    #pragma unroll
    for (int j = 0; j < 2; ++j) {
        float2 vi = unpack2(zi2[j]), vf = unpack2(zf2[j]);
        float2 vg = unpack2(zg2[j]), vo = unpack2(zo2[j]);
        float cA = sigm(vf.x) * cl[2*j]   + sigm(vi.x) * tanhf_(vg.x);
        float cB = sigm(vf.y) * cl[2*j+1] + sigm(vi.y) * tanhf_(vg.y);
        cl[2*j] = cA; cl[2*j+1] = cB;
        hl[2*j]   = sigm(vo.x) * tanhf_(cA);
        hl[2*j+1] = sigm(vo.y) * tanhf_(cB);
    }
    *(float4*)(hL + gu * HPAD + 4 * q) = make_float4(hl[0], hl[1], hl[2], hl[3]);
}

__global__ void __launch_bounds__(NTH, 1)
lstm3_kernel(
    const float* __restrict__ x,
    const float* __restrict__ W0, const float* __restrict__ U0, const float* __restrict__ b0,
    const float* __restrict__ W1, const float* __restrict__ U1, const float* __restrict__ b1,
    const float* __restrict__ W2, const float* __restrict__ U2, const float* __restrict__ b2,
    const float* __restrict__ Wfc, const float* __restrict__ bfc,
    float* __restrict__ out, int B)
{
    extern __shared__ __align__(16) unsigned char smraw[];
    float* hs = (float*)smraw;
    u64*   zs = (u64*)(smraw + HS_BYTES);
    float* xs = (float*)(smraw + HS_BYTES + ZS_BYTES);

    const int tid  = threadIdx.x;
    const int brow = blockIdx.x * BT;

    // zero h state
    for (int i = tid; i < 3 * HHID * HPAD; i += NTH) hs[i] = 0.0f;
    // stage x tile: coalesced read, transpose to [t][b]
    for (int i = tid; i < TSEQ * BT; i += NTH) {
        int b = i / TSEQ, t = i - b * TSEQ, gb = brow + b;
        xs[t * BT + b] = (gb < B) ? x[gb * TSEQ + t] : 0.0f;
    }
    __syncthreads();

    const int gu = tid % HHID;    // unit for gate phase
    const int q  = tid / HHID;    // batch quad for gate phase

    float c0[4], c1[4], c2[4];
    #pragma unroll
    for (int i = 0; i < 4; ++i) { c0[i] = 0.f; c1[i] = 0.f; c2[i] = 0.f; }

    float* h0s = hs;
    float* h1s = hs + HHID * HPAD;
    float* h2s = hs + 2 * HHID * HPAD;

    for (int t = 0; t < TSEQ; ++t) {
        u64 acc[8];

        // ---- layer 0: z = x_t*W0 + h0@U0 + b0 (input dim 1 -> rank-1 term) ----
        set_bias(acc, b0, tid);
        {
            float w = __ldg(W0 + tid);
            u64 wp = pack2(w, w);
            const ulonglong2* xp = (const ulonglong2*)(xs + t * BT);
            ulonglong2 a = xp[0], b = xp[1], c = xp[2], d = xp[3];
            acc[0] = ffma2(a.x, wp, acc[0]); acc[1] = ffma2(a.y, wp, acc[1]);
            acc[2] = ffma2(b.x, wp, acc[2]); acc[3] = ffma2(b.y, wp, acc[3]);
            acc[4] = ffma2(c.x, wp, acc[4]); acc[5] = ffma2(c.y, wp, acc[5]);
            acc[6] = ffma2(d.x, wp, acc[6]); acc[7] = ffma2(d.y, wp, acc[7]);
        }
        mv(acc, h0s, U0, tid);
        z_store(zs, acc, tid);
        __syncthreads();
        gate_phase(zs, gu, q, c0, h0s);
        __syncthreads();

        // ---- layer 1: z = h0@W1 + h1@U1 + b1 ----
        set_bias(acc, b1, tid);
        mv(acc, h0s, W1, tid);
        mv(acc, h1s, U1, tid);
        z_store(zs, acc, tid);
        __syncthreads();
        gate_phase(zs, gu, q, c1, h1s);
        __syncthreads();

        // ---- layer 2: z = h1@W2 + h2@U2 + b2 ----
        set_bias(acc, b2, tid);
        mv(acc, h1s, W2, tid);
        mv(acc, h2s, U2, tid);
        z_store(zs, acc, tid);
        __syncthreads();
        gate_phase(zs, gu, q, c2, h2s);
        __syncthreads();
    }

    // ---- dense head: y = tanh(h2 @ Wfc + bfc) ----
    for (int idx = tid; idx < BT * 400; idx += NTH) {   // 8 iters
        int b = idx / 400, j = idx - b * 400;
        int gb = brow + b;
        if (gb >= B) continue;
        float s = __ldg(bfc + j);
        #pragma unroll 4
        for (int k = 0; k < HHID; ++k)
            s = __fmaf_rn(h2s[k * HPAD + b], __ldg(Wfc + k * 400 + j), s);
        out[gb * 400 + j] = tanhf_(s);
    }
}

extern "C" void kernel_launch(void* const* d_in, const int* in_sizes, int n_in,
                              void* d_out, int out_size) {
    const float* x   = (const float*)d_in[0];
    const float* W0  = (const float*)d_in[1];
    const float* U0  = (const float*)d_in[2];
    const float* b0  = (const float*)d_in[3];
    const float* W1  = (const float*)d_in[4];
    const float* U1  = (const float*)d_in[5];
    const float* b1  = (const float*)d_in[6];
    const float* W2  = (const float*)d_in[7];
    const float* U2  = (const float*)d_in[8];
    const float* b2  = (const float*)d_in[9];
    const float* Wfc = (const float*)d_in[10];
    const float* bfc = (const float*)d_in[11];
    float* out = (float*)d_out;

    int B = in_sizes[0] / TSEQ;
    int nblk = (B + BT - 1) / BT;
    cudaFuncSetAttribute(lstm3_kernel, cudaFuncAttributeMaxDynamicSharedMemorySize, SMEM_BYTES);
    lstm3_kernel<<<nblk, NTH, SMEM_BYTES>>>(x, W0, U0, b0, W1, U1, b1, W2, U2, b2,
                                            Wfc, bfc, out, B);
}

// round 17
// speedup vs baseline: 2.7494x; 2.2381x over previous
#include <cuda_runtime.h>

#define TSEQ 100
#define HHID 200
#define BT   32          // batch rows per CTA
#define NTH  800         // 2 halves x 2 gate-pairs x 200 units
#define HROW 36          // floats per h row (32 + pad, 16B aligned)
#define ZROW 9           // u64 per z-exchange row (8 + pad, 2-way conflicts)

typedef unsigned long long u64;

#define HS_BYTES (3 * HHID * HROW * 4)   // 86400: h state, [layer][unit][batch]
#define ZPLANE   (400 * ZROW * 8)        // 28800 per gate plane
#define CS_BYTES (3 * 16 * 400 * 4)      // 76800: c state, [layer][j][owner]
#define ZI_OFF   HS_BYTES
#define ZF_OFF   (ZI_OFF + ZPLANE)
#define CS_OFF   (ZF_OFF + ZPLANE)
#define XB_OFF   (CS_OFF + CS_BYTES)
#define SMEM_BYTES (XB_OFF + BT * 4)     // 220928 B

__device__ __forceinline__ u64 pack2(float a, float b) {
    u64 r; asm("mov.b64 %0, {%1, %2};" : "=l"(r) : "f"(a), "f"(b)); return r;
}
__device__ __forceinline__ float2 unpack2(u64 v) {
    float2 f; asm("mov.b64 {%0, %1}, %2;" : "=f"(f.x), "=f"(f.y) : "l"(v)); return f;
}
__device__ __forceinline__ u64 ffma2(u64 a, u64 b, u64 c) {
    u64 d; asm("fma.rn.f32x2 %0, %1, %2, %3;" : "=l"(d) : "l"(a), "l"(b), "l"(c)); return d;
}
__device__ __forceinline__ float ex2f(float x) {
    float y; asm("ex2.approx.ftz.f32 %0, %1;" : "=f"(y) : "f"(x)); return y;
}
__device__ __forceinline__ float rcpf(float x) {
    float y; asm("rcp.approx.ftz.f32 %0, %1;" : "=f"(y) : "f"(x)); return y;
}
__device__ __forceinline__ float sigm(float z)  { return rcpf(1.0f + ex2f(-1.44269504f * z)); }
__device__ __forceinline__ float tanhf_(float z){ return __fmaf_rn(2.0f, rcpf(1.0f + ex2f(-2.88539008f * z)), -1.0f); }

// accA/accB (each: 16 batch rows as 8 f32x2) += h @ (colA, colB) of M
__device__ __forceinline__ void mv(u64 aA[8], u64 aB[8],
    const float* __restrict__ hL, const float* __restrict__ M,
    int coloff, int hoff)
{
    const float* Mp = M + coloff;
    #pragma unroll 2
    for (int k = 0; k < HHID; ++k) {
        float wa = __ldg(Mp + k * 800);
        float wb = __ldg(Mp + k * 800 + 200);
        const ulonglong2* hp = (const ulonglong2*)(hL + k * HROW + hoff);
        ulonglong2 A = hp[0], Bv = hp[1], C = hp[2], D = hp[3];
        u64 wap = pack2(wa, wa), wbp = pack2(wb, wb);
        aA[0] = ffma2(A.x,  wap, aA[0]); aB[0] = ffma2(A.x,  wbp, aB[0]);
        aA[1] = ffma2(A.y,  wap, aA[1]); aB[1] = ffma2(A.y,  wbp, aB[1]);
        aA[2] = ffma2(Bv.x, wap, aA[2]); aB[2] = ffma2(Bv.x, wbp, aB[2]);
        aA[3] = ffma2(Bv.y, wap, aA[3]); aB[3] = ffma2(Bv.y, wbp, aB[3]);
        aA[4] = ffma2(C.x,  wap, aA[4]); aB[4] = ffma2(C.x,  wbp, aB[4]);
        aA[5] = ffma2(C.y,  wap, aA[5]); aB[5] = ffma2(C.y,  wbp, aB[5]);
        aA[6] = ffma2(D.x,  wap, aA[6]); aB[6] = ffma2(D.x,  wbp, aB[6]);
        aA[7] = ffma2(D.y,  wap, aA[7]); aB[7] = ffma2(D.y,  wbp, aB[7]);
    }
}

__device__ __forceinline__ void set_bias(u64 aA[8], u64 aB[8],
    const float* __restrict__ bias, int coloff)
{
    float ba = __ldg(bias + coloff), bb = __ldg(bias + coloff + 200);
    u64 bap = pack2(ba, ba), bbp = pack2(bb, bb);
    #pragma unroll
    for (int j = 0; j < 8; ++j) { aA[j] = bap; aB[j] = bbp; }
}

// pair-0 (i,f) threads publish z; pair-1 (g,o) threads consume + update cells
__device__ __forceinline__ void z_store(unsigned char* sm, const u64 aA[8], const u64 aB[8], int owner)
{
    u64* zi = (u64*)(sm + ZI_OFF) + owner * ZROW;
    u64* zf = (u64*)(sm + ZF_OFF) + owner * ZROW;
    #pragma unroll
    for (int j = 0; j < 8; ++j) { zi[j] = aA[j]; zf[j] = aB[j]; }
}

__device__ __forceinline__ void gate_phase(unsigned char* sm, int layer,
    const u64 aG[8], const u64 aO[8], int owner, int u, int hoff, float* __restrict__ hL)
{
    const u64* zi = (const u64*)(sm + ZI_OFF) + owner * ZROW;
    const u64* zf = (const u64*)(sm + ZF_OFF) + owner * ZROW;
    float* cbase = (float*)(sm + CS_OFF + layer * (16 * 400 * 4)) + owner;
    float hl[16];
    #pragma unroll
    for (int j = 0; j < 8; ++j) {
        float2 vi = unpack2(zi[j]), vf = unpack2(zf[j]);
        float2 vg = unpack2(aG[j]), vo = unpack2(aO[j]);
        float c0 = cbase[(2*j)   * 400];
        float c1 = cbase[(2*j+1) * 400];
        float cA = sigm(vf.x) * c0 + sigm(vi.x) * tanhf_(vg.x);
        float cB = sigm(vf.y) * c1 + sigm(vi.y) * tanhf_(vg.y);
        cbase[(2*j)   * 400] = cA;
        cbase[(2*j+1) * 400] = cB;
        hl[2*j]   = sigm(vo.x) * tanhf_(cA);
        hl[2*j+1] = sigm(vo.y) * tanhf_(cB);
    }
    float4* hv = (float4*)(hL + u * HROW + hoff);
    #pragma unroll
    for (int q = 0; q < 4; ++q) hv[q] = ((const float4*)hl)[q];
}

__global__ void __launch_bounds__(NTH, 1)
lstm3_kernel(
    const float* __restrict__ x,
    const float* __restrict__ W0, const float* __restrict__ U0, const float* __restrict__ b0,
    const float* __restrict__ W1, const float* __restrict__ U1, const float* __restrict__ b1,
    const float* __restrict__ W2, const float* __restrict__ U2, const float* __restrict__ b2,
    const float* __restrict__ Wfc, const float* __restrict__ bfc,
    float* __restrict__ out, int B)
{
    extern __shared__ __align__(16) unsigned char sm[];
    float* hs   = (float*)sm;
    float* xbuf = (float*)(sm + XB_OFF);

    const int tid  = threadIdx.x;
    const int brow = blockIdx.x * BT;

    const int half   = tid / 400;          // which 16-row batch half
    const int rem    = tid - half * 400;
    const int pair   = rem / 200;          // 0: gates i,f   1: gates g,o
    const int u      = rem - pair * 200;   // hidden unit
    const int owner  = half * 200 + u;
    const int coloff = pair * 400 + u;     // weight columns coloff, coloff+200
    const int hoff   = half * 16;          // float offset into h rows

    // zero h and c state
    for (int i = tid; i < 3 * HHID * HROW; i += NTH) hs[i] = 0.0f;
    float* cs = (float*)(sm + CS_OFF);
    for (int i = tid; i < 3 * 16 * 400; i += NTH) cs[i] = 0.0f;
    __syncthreads();

    float* h0s = hs;
    float* h1s = hs + HHID * HROW;
    float* h2s = hs + 2 * HHID * HROW;

    for (int t = 0; t < TSEQ; ++t) {
        if (tid < BT) {
            int gb = brow + tid;
            xbuf[tid] = (gb < B) ? x[gb * TSEQ + t] : 0.0f;
        }
        __syncthreads();

        u64 aA[8], aB[8];

        // ---- layer 0: z = x_t*W0 + h0@U0 + b0 ----
        set_bias(aA, aB, b0, coloff);
        {
            float wa = __ldg(W0 + coloff), wb = __ldg(W0 + coloff + 200);
            u64 wap = pack2(wa, wa), wbp = pack2(wb, wb);
            const ulonglong2* xp = (const ulonglong2*)(xbuf + hoff);
            ulonglong2 A = xp[0], Bv = xp[1], C = xp[2], D = xp[3];
            u64 xv[8] = { A.x, A.y, Bv.x, Bv.y, C.x, C.y, D.x, D.y };
            #pragma unroll
            for (int j = 0; j < 8; ++j) {
                aA[j] = ffma2(xv[j], wap, aA[j]);
                aB[j] = ffma2(xv[j], wbp, aB[j]);
            }
        }
        mv(aA, aB, h0s, U0, coloff, hoff);
        if (pair == 0) z_store(sm, aA, aB, owner);
        __syncthreads();
        if (pair == 1) gate_phase(sm, 0, aA, aB, owner, u, hoff, h0s);
        __syncthreads();

        // ---- layer 1: z = h0@W1 + h1@U1 + b1 ----
        set_bias(aA, aB, b1, coloff);
        mv(aA, aB, h0s, W1, coloff, hoff);
        mv(aA, aB, h1s, U1, coloff, hoff);
        if (pair == 0) z_store(sm, aA, aB, owner);
        __syncthreads();
        if (pair == 1) gate_phase(sm, 1, aA, aB, owner, u, hoff, h1s);
        __syncthreads();

        // ---- layer 2: z = h1@W2 + h2@U2 + b2 ----
        set_bias(aA, aB, b2, coloff);
        mv(aA, aB, h1s, W2, coloff, hoff);
        mv(aA, aB, h2s, U2, coloff, hoff);
        if (pair == 0) z_store(sm, aA, aB, owner);
        __syncthreads();
        if (pair == 1) gate_phase(sm, 2, aA, aB, owner, u, hoff, h2s);
        __syncthreads();
    }

    // ---- dense head: y = tanh(h2 @ Wfc + bfc) ----
    for (int idx = tid; idx < BT * 400; idx += NTH) {   // 16 iters
        int b = idx / 400, j = idx - b * 400;
        int gb = brow + b;
        if (gb >= B) continue;
        float s = __ldg(bfc + j);
        #pragma unroll 4
        for (int k = 0; k < HHID; ++k)
            s = __fmaf_rn(h2s[k * HROW + b], __ldg(Wfc + k * 400 + j), s);
        out[gb * 400 + j] = tanhf_(s);
    }
}

extern "C" void kernel_launch(void* const* d_in, const int* in_sizes, int n_in,
                              void* d_out, int out_size) {
    const float* x   = (const float*)d_in[0];
    const float* W0  = (const float*)d_in[1];
    const float* U0  = (const float*)d_in[2];
    const float* b0  = (const float*)d_in[3];
    const float* W1  = (const float*)d_in[4];
    const float* U1  = (const float*)d_in[5];
    const float* b1  = (const float*)d_in[6];
    const float* W2  = (const float*)d_in[7];
    const float* U2  = (const float*)d_in[8];
    const float* b2  = (const float*)d_in[9];
    const float* Wfc = (const float*)d_in[10];
    const float* bfc = (const float*)d_in[11];
    float* out = (float*)d_out;

    int B = in_sizes[0] / TSEQ;
    int nblk = (B + BT - 1) / BT;
    cudaFuncSetAttribute(lstm3_kernel, cudaFuncAttributeMaxDynamicSharedMemorySize, SMEM_BYTES);
    lstm3_kernel<<<nblk, NTH, SMEM_BYTES>>>(x, W0, U0, b0, W1, U1, b1, W2, U2, b2,
                                            Wfc, bfc, out, B);
}